// round 1
// baseline (speedup 1.0000x reference)
#include <cuda_runtime.h>
#include <math.h>

#define Bn 8
#define Cn 64
#define HW 65536
#define Sn 2048
#define OUTC 16
#define INV_TAU (1.0f/0.07f)

// Scratch for normalized embeddings: [B, S, 16] each (1 MB each)
__device__ float g_fq[Bn * Sn * OUTC];
__device__ float g_fk[Bn * Sn * OUTC];

// ---------------------------------------------------------------------------
// Kernel 1: per (map, b, s) row — gather diff, 64->64 relu MLP, 64->16, L2 norm
// grid = 2*B*S blocks of 64 threads
// ---------------------------------------------------------------------------
__global__ void ns_mlp_kernel(const float* __restrict__ fq,
                              const float* __restrict__ fk,
                              const float* __restrict__ W0,
                              const float* __restrict__ b0,
                              const float* __restrict__ W1,
                              const float* __restrict__ b1,
                              const int*   __restrict__ c_ids,
                              const int*   __restrict__ n_ids) {
    __shared__ float sdiff[64];
    __shared__ float sh[64];

    int gid = blockIdx.x;
    int map = gid >> 14;          // 0 = f_q, 1 = f_k   (B*S = 16384)
    int bs  = gid & 16383;
    int b   = bs >> 11;
    int s   = bs & 2047;

    const float* feat = map ? fk : fq;
    float* out = map ? g_fk : g_fq;

    int t = threadIdx.x;          // 0..63 = channel / hidden unit
    int ic = c_ids[s];
    int in_ = n_ids[s];

    const float* base = feat + ((size_t)b * Cn + t) * HW;
    sdiff[t] = base[ic] - base[in_];
    __syncthreads();

    // hidden[t] = relu(b0[t] + sum_c diff[c] * W0[c,t])
    float acc = b0[t];
#pragma unroll
    for (int c = 0; c < 64; c++)
        acc = fmaf(sdiff[c], __ldg(&W0[c * 64 + t]), acc);
    sh[t] = fmaxf(acc, 0.0f);
    __syncthreads();

    if (t < 16) {
        float a = b1[t];
#pragma unroll
        for (int j = 0; j < 64; j++)
            a = fmaf(sh[j], __ldg(&W1[j * 16 + t]), a);
        // L2 norm over the 16 outputs (lanes 0..15 of warp 0)
        float sq = a * a;
#pragma unroll
        for (int o = 8; o > 0; o >>= 1)
            sq += __shfl_xor_sync(0x0000FFFFu, sq, o, 16);
        float norm = sqrtf(sq);
        out[((size_t)b * Sn + s) * OUTC + t] = a / (norm + 1e-7f);
    }
}

// ---------------------------------------------------------------------------
// Kernel 2: PatchNCE loss.
//   loss_row(b,s) = logsumexp_t( d_st / tau ) - d_ss / tau
//   with d_st = dot(fq[b,s,:], fk[b,t,:]).  (l_pos == diagonal; masking and
//   concat cancel exactly.)  Fixed shift exp((d-1)/tau) since |d| <= 1.
// grid = B * (S/32) blocks, 256 threads (8 warps x 4 rows each)
// smem = full fk[b] tile: 2048*16*4 = 128 KB
// ---------------------------------------------------------------------------
__global__ void loss_kernel(float* __restrict__ out) {
    extern __shared__ float shk[];   // [2048][16]
    int b    = blockIdx.x >> 6;      // 64 tiles per batch
    int tile = blockIdx.x & 63;

    const float* fkb = g_fk + (size_t)b * Sn * OUTC;
    const float* fqb = g_fq + (size_t)b * Sn * OUTC;

    // Stage fk[b] into shared (float4, coalesced)
    float4* shk4 = reinterpret_cast<float4*>(shk);
    const float4* fkb4 = reinterpret_cast<const float4*>(fkb);
    for (int i = threadIdx.x; i < Sn * 4; i += blockDim.x)
        shk4[i] = fkb4[i];
    __syncthreads();

    int w    = threadIdx.x >> 5;
    int lane = threadIdx.x & 31;
    int s0   = tile * 32 + w * 4;

    // 4 query rows per warp, full copies in registers (broadcast L1 loads)
    float q[4][16];
#pragma unroll
    for (int r = 0; r < 4; r++) {
        const float* qr = fqb + (size_t)(s0 + r) * OUTC;
#pragma unroll
        for (int c = 0; c < 16; c++) q[r][c] = __ldg(&qr[c]);
    }

    float sum[4] = {0.f, 0.f, 0.f, 0.f};

    for (int t = lane; t < Sn; t += 32) {
        float4 k0 = shk4[t * 4 + 0];
        float4 k1 = shk4[t * 4 + 1];
        float4 k2 = shk4[t * 4 + 2];
        float4 k3 = shk4[t * 4 + 3];
        float kk[16] = {k0.x, k0.y, k0.z, k0.w,
                        k1.x, k1.y, k1.z, k1.w,
                        k2.x, k2.y, k2.z, k2.w,
                        k3.x, k3.y, k3.z, k3.w};
#pragma unroll
        for (int r = 0; r < 4; r++) {
            float d = 0.f;
#pragma unroll
            for (int c = 0; c < 16; c++)
                d = fmaf(q[r][c], kk[c], d);
            sum[r] += __expf((d - 1.0f) * INV_TAU);
        }
    }

    // warp-reduce the 4 row sums
#pragma unroll
    for (int r = 0; r < 4; r++) {
#pragma unroll
        for (int o = 16; o > 0; o >>= 1)
            sum[r] += __shfl_xor_sync(0xFFFFFFFFu, sum[r], o);
    }

    if (lane == 0) {
        float acc = 0.f;
#pragma unroll
        for (int r = 0; r < 4; r++) {
            int s = s0 + r;
            const float* ks = shk + (size_t)s * OUTC;
            float d = 0.f;
#pragma unroll
            for (int c = 0; c < 16; c++)
                d = fmaf(q[r][c], ks[c], d);
            // lse = log(sum) + 1/tau ;  loss_row = lse - d/tau
            acc += logf(sum[r]) + (1.0f - d) * INV_TAU;
        }
        atomicAdd(out, acc * (1.0f / (float)(Bn * Sn)));
    }
}

__global__ void zero_kernel(float* out) {
    if (threadIdx.x == 0) out[0] = 0.0f;
}

// ---------------------------------------------------------------------------
extern "C" void kernel_launch(void* const* d_in, const int* in_sizes, int n_in,
                              void* d_out, int out_size) {
    const float* f_q  = (const float*)d_in[0];
    const float* f_k  = (const float*)d_in[1];
    const float* W0   = (const float*)d_in[2];
    const float* b0   = (const float*)d_in[3];
    const float* W1   = (const float*)d_in[4];
    const float* b1   = (const float*)d_in[5];
    const int*   c_id = (const int*)d_in[6];
    const int*   n_id = (const int*)d_in[7];
    float* out = (float*)d_out;

    // allow 128 KB dynamic shared for the loss kernel (idempotent)
    cudaFuncSetAttribute(loss_kernel,
                         cudaFuncAttributeMaxDynamicSharedMemorySize,
                         Sn * OUTC * (int)sizeof(float));

    ns_mlp_kernel<<<2 * Bn * Sn, 64>>>(f_q, f_k, W0, b0, W1, b1, c_id, n_id);
    zero_kernel<<<1, 32>>>(out);
    loss_kernel<<<Bn * (Sn / 32), 256, Sn * OUTC * (int)sizeof(float)>>>(out);
}

// round 2
// speedup vs baseline: 1.2777x; 1.2777x over previous
#include <cuda_runtime.h>
#include <math.h>

#define Bn 8
#define Cn 64
#define HW 65536
#define Sn 2048
#define OUTC 16
#define INV_TAU (1.0f/0.07f)

// Scratch: diffs [16 mb][64 c][2048 s] = 8 MB, embeddings 1 MB each
__device__ float g_diff[2 * Bn * Cn * Sn];
__device__ float g_fq[Bn * Sn * OUTC];
__device__ float g_fk[Bn * Sn * OUTC];

// ---------------------------------------------------------------------------
// Kernel A: gather + diff.  grid = 2*B*C = 1024 blocks, 256 threads.
// Block owns one (map, b, channel) plane; thread j owns center j:
// loads the center ONCE, then 8 neighbor loads -> 8 diffs.
// Writes g_diff[mb][c][s] coalesced (s = off*256 + j, j = lane-contiguous).
// ---------------------------------------------------------------------------
__global__ void gather_diff_kernel(const float* __restrict__ fq,
                                   const float* __restrict__ fk,
                                   const int*   __restrict__ c_ids,
                                   const int*   __restrict__ n_ids) {
    int gid = blockIdx.x;
    int map = gid >> 9;             // / (Bn*Cn)
    int bc  = gid & 511;
    int b   = bc >> 6;
    int c   = bc & 63;

    const float* feat = (map ? fk : fq) + ((size_t)b * Cn + c) * HW;
    float* dst = g_diff + ((size_t)(map * Bn + b) * Cn + c) * Sn;

    int j = threadIdx.x;            // center index 0..255
    float fc = __ldg(&feat[c_ids[j]]);

#pragma unroll
    for (int off = 0; off < 8; off++) {
        int s = off * 256 + j;
        float d = fc - __ldg(&feat[n_ids[s]]);
        dst[s] = d;
    }
}

// ---------------------------------------------------------------------------
// Kernel B: MLP + L2-normalize.  grid = 16 mb * 16 chunks = 256 blocks,
// 128 threads; each thread owns one row (s) entirely.
// Dyn smem: x-tile [128][68] + W0^T [64][64] + W1 [64][16] + biases.
// ---------------------------------------------------------------------------
#define XPAD 68
__global__ void mlp_kernel(const float* __restrict__ W0,
                           const float* __restrict__ b0,
                           const float* __restrict__ W1,
                           const float* __restrict__ b1) {
    extern __shared__ float smem[];
    float* sx  = smem;                       // 128*68
    float* sW0 = sx + 128 * XPAD;            // 64*64  (transposed: [t][c])
    float* sW1 = sW0 + 64 * 64;              // 64*16  ([t][o])
    float* sb0 = sW1 + 64 * 16;              // 64
    float* sb1 = sb0 + 64;                   // 16

    int mb = blockIdx.x >> 4;
    int s0 = (blockIdx.x & 15) * 128;
    int tid = threadIdx.x;

    const float* src = g_diff + (size_t)mb * Cn * Sn;

    for (int i = tid; i < 4096; i += 128) {
        int c = i >> 6, t = i & 63;
        sW0[t * 64 + c] = __ldg(&W0[i]);     // W0 is [c][t] row-major
    }
    for (int i = tid; i < 1024; i += 128) sW1[i] = __ldg(&W1[i]);
    if (tid < 64) sb0[tid] = __ldg(&b0[tid]);
    if (tid < 16) sb1[tid] = __ldg(&b1[tid]);

    // load x tile transposed: coalesced reads of g_diff[c][s0+s]
    for (int i = tid; i < 64 * 128; i += 128) {
        int c = i >> 7, s = i & 127;
        sx[s * XPAD + c] = src[(size_t)c * Sn + s0 + s];
    }
    __syncthreads();

    float4 xr[16];
#pragma unroll
    for (int i = 0; i < 16; i++)
        xr[i] = *reinterpret_cast<float4*>(&sx[tid * XPAD + i * 4]);

    float o[16];
#pragma unroll
    for (int i = 0; i < 16; i++) o[i] = sb1[i];

#pragma unroll 4
    for (int t = 0; t < 64; t++) {
        float acc0 = 0.f, acc1 = 0.f, acc2 = 0.f, acc3 = 0.f;
#pragma unroll
        for (int cc = 0; cc < 16; cc += 4) {
            float4 wa = *reinterpret_cast<float4*>(&sW0[t * 64 + (cc + 0) * 4]);
            float4 wb = *reinterpret_cast<float4*>(&sW0[t * 64 + (cc + 1) * 4]);
            float4 wc = *reinterpret_cast<float4*>(&sW0[t * 64 + (cc + 2) * 4]);
            float4 wd = *reinterpret_cast<float4*>(&sW0[t * 64 + (cc + 3) * 4]);
            float4 xa = xr[cc + 0], xb = xr[cc + 1], xc = xr[cc + 2], xd = xr[cc + 3];
            acc0 = fmaf(xa.x, wa.x, acc0); acc0 = fmaf(xa.y, wa.y, acc0);
            acc0 = fmaf(xa.z, wa.z, acc0); acc0 = fmaf(xa.w, wa.w, acc0);
            acc1 = fmaf(xb.x, wb.x, acc1); acc1 = fmaf(xb.y, wb.y, acc1);
            acc1 = fmaf(xb.z, wb.z, acc1); acc1 = fmaf(xb.w, wb.w, acc1);
            acc2 = fmaf(xc.x, wc.x, acc2); acc2 = fmaf(xc.y, wc.y, acc2);
            acc2 = fmaf(xc.z, wc.z, acc2); acc2 = fmaf(xc.w, wc.w, acc2);
            acc3 = fmaf(xd.x, wd.x, acc3); acc3 = fmaf(xd.y, wd.y, acc3);
            acc3 = fmaf(xd.z, wd.z, acc3); acc3 = fmaf(xd.w, wd.w, acc3);
        }
        float h = fmaxf((acc0 + acc1) + (acc2 + acc3) + sb0[t], 0.f);
#pragma unroll
        for (int oo = 0; oo < 4; oo++) {
            float4 w1 = *reinterpret_cast<float4*>(&sW1[t * 16 + oo * 4]);
            o[oo * 4 + 0] = fmaf(h, w1.x, o[oo * 4 + 0]);
            o[oo * 4 + 1] = fmaf(h, w1.y, o[oo * 4 + 1]);
            o[oo * 4 + 2] = fmaf(h, w1.z, o[oo * 4 + 2]);
            o[oo * 4 + 3] = fmaf(h, w1.w, o[oo * 4 + 3]);
        }
    }

    float sq = 0.f;
#pragma unroll
    for (int i = 0; i < 16; i++) sq = fmaf(o[i], o[i], sq);
    float inv = 1.0f / (sqrtf(sq) + 1e-7f);

    float* dst = (mb < Bn ? g_fq + (size_t)mb * Sn * OUTC
                          : g_fk + (size_t)(mb - Bn) * Sn * OUTC)
                 + (size_t)(s0 + tid) * OUTC;
#pragma unroll
    for (int oo = 0; oo < 4; oo++) {
        float4 v = make_float4(o[oo * 4 + 0] * inv, o[oo * 4 + 1] * inv,
                               o[oo * 4 + 2] * inv, o[oo * 4 + 3] * inv);
        *reinterpret_cast<float4*>(&dst[oo * 4]) = v;
    }
}

// ---------------------------------------------------------------------------
// Kernel C: PatchNCE loss.
//   loss_row(b,s) = logsumexp_t( d_st / tau ) - d_ss / tau,  |d| <= 1 so
//   fixed shift exp((d-1)/tau).  512 threads = 16 warps x 4 rows = 64 rows.
//   grid = B * 32, smem = fk[b] (128 KB).
// ---------------------------------------------------------------------------
__global__ void loss_kernel(float* __restrict__ out) {
    extern __shared__ float shk[];   // [2048][16]
    int b    = blockIdx.x >> 5;      // 32 tiles per batch
    int tile = blockIdx.x & 31;

    const float* fkb = g_fk + (size_t)b * Sn * OUTC;
    const float* fqb = g_fq + (size_t)b * Sn * OUTC;

    float4* shk4 = reinterpret_cast<float4*>(shk);
    const float4* fkb4 = reinterpret_cast<const float4*>(fkb);
    for (int i = threadIdx.x; i < Sn * 4; i += blockDim.x)
        shk4[i] = fkb4[i];
    __syncthreads();

    int w    = threadIdx.x >> 5;
    int lane = threadIdx.x & 31;
    int s0   = tile * 64 + w * 4;

    float q[4][16];
#pragma unroll
    for (int r = 0; r < 4; r++) {
        const float* qr = fqb + (size_t)(s0 + r) * OUTC;
#pragma unroll
        for (int c = 0; c < 16; c++) q[r][c] = __ldg(&qr[c]);
    }

    float sum[4] = {0.f, 0.f, 0.f, 0.f};

    for (int t = lane; t < Sn; t += 32) {
        float4 k0 = shk4[t * 4 + 0];
        float4 k1 = shk4[t * 4 + 1];
        float4 k2 = shk4[t * 4 + 2];
        float4 k3 = shk4[t * 4 + 3];
        float kk[16] = {k0.x, k0.y, k0.z, k0.w,
                        k1.x, k1.y, k1.z, k1.w,
                        k2.x, k2.y, k2.z, k2.w,
                        k3.x, k3.y, k3.z, k3.w};
#pragma unroll
        for (int r = 0; r < 4; r++) {
            float d = 0.f;
#pragma unroll
            for (int c = 0; c < 16; c++)
                d = fmaf(q[r][c], kk[c], d);
            sum[r] += __expf((d - 1.0f) * INV_TAU);
        }
    }

#pragma unroll
    for (int r = 0; r < 4; r++) {
#pragma unroll
        for (int o = 16; o > 0; o >>= 1)
            sum[r] += __shfl_xor_sync(0xFFFFFFFFu, sum[r], o);
    }

    if (lane == 0) {
        float acc = 0.f;
#pragma unroll
        for (int r = 0; r < 4; r++) {
            int s = s0 + r;
            const float* ks = shk + (size_t)s * OUTC;
            float d = 0.f;
#pragma unroll
            for (int c = 0; c < 16; c++)
                d = fmaf(q[r][c], ks[c], d);
            acc += logf(sum[r]) + (1.0f - d) * INV_TAU;
        }
        atomicAdd(out, acc * (1.0f / (float)(Bn * Sn)));
    }
}

__global__ void zero_kernel(float* out) {
    if (threadIdx.x == 0) out[0] = 0.0f;
}

// ---------------------------------------------------------------------------
extern "C" void kernel_launch(void* const* d_in, const int* in_sizes, int n_in,
                              void* d_out, int out_size) {
    const float* f_q  = (const float*)d_in[0];
    const float* f_k  = (const float*)d_in[1];
    const float* W0   = (const float*)d_in[2];
    const float* b0   = (const float*)d_in[3];
    const float* W1   = (const float*)d_in[4];
    const float* b1   = (const float*)d_in[5];
    const int*   c_id = (const int*)d_in[6];
    const int*   n_id = (const int*)d_in[7];
    float* out = (float*)d_out;

    int mlp_smem = (128 * XPAD + 64 * 64 + 64 * 16 + 64 + 16) * (int)sizeof(float);
    cudaFuncSetAttribute(mlp_kernel,
                         cudaFuncAttributeMaxDynamicSharedMemorySize, mlp_smem);
    cudaFuncSetAttribute(loss_kernel,
                         cudaFuncAttributeMaxDynamicSharedMemorySize,
                         Sn * OUTC * (int)sizeof(float));

    gather_diff_kernel<<<2 * Bn * Cn, 256>>>(f_q, f_k, c_id, n_id);
    mlp_kernel<<<16 * 16, 128, mlp_smem>>>(W0, b0, W1, b1);
    zero_kernel<<<1, 32>>>(out);
    loss_kernel<<<Bn * 32, 512, Sn * OUTC * (int)sizeof(float)>>>(out);
}

// round 3
// speedup vs baseline: 1.9390x; 1.5176x over previous
#include <cuda_runtime.h>
#include <math.h>

#define Bn 8
#define Cn 64
#define HW 65536
#define Sn 2048
#define OUTC 16

#define F_INV_TAU   14.2857142857142857f          /* 1/0.07 */
#define F_SCALE     20.6096954f                   /* log2(e)/0.07 */
#define F_LN2       0.69314718056f

// f32x2 packed helpers ------------------------------------------------------
typedef unsigned long long ull;
__device__ __forceinline__ ull pack2(float lo, float hi) {
    ull r;
    asm("mov.b64 %0, {%1, %2};" : "=l"(r) : "r"(__float_as_uint(lo)), "r"(__float_as_uint(hi)));
    return r;
}
__device__ __forceinline__ void unpack2(ull v, float& lo, float& hi) {
    unsigned a, b;
    asm("mov.b64 {%0, %1}, %2;" : "=r"(a), "=r"(b) : "l"(v));
    lo = __uint_as_float(a); hi = __uint_as_float(b);
}
#define FMA2(d, a, b) asm("fma.rn.f32x2 %0, %1, %2, %3;" : "=l"(d) : "l"(a), "l"(b), "l"(d))
#define ADD2(d, a)    asm("add.rn.f32x2 %0, %1, %2;"     : "=l"(d) : "l"(a), "l"(d))
__device__ __forceinline__ float ex2f(float x) {
    float y; asm("ex2.approx.f32 %0, %1;" : "=f"(y) : "f"(x)); return y;
}
__device__ __forceinline__ float lg2f(float x) {
    float y; asm("lg2.approx.f32 %0, %1;" : "=f"(y) : "f"(x)); return y;
}

// Scratch
__device__ float g_diff[2 * Bn * Cn * Sn];      // 8 MB
__device__ float g_fq[Bn * Sn * OUTC];
__device__ float g_fk[Bn * Sn * OUTC];

// ---------------------------------------------------------------------------
// Kernel A: gather + diff.  grid = 2*B*C = 1024 blocks, 256 threads.
// ---------------------------------------------------------------------------
__global__ void gather_diff_kernel(const float* __restrict__ fq,
                                   const float* __restrict__ fk,
                                   const int*   __restrict__ c_ids,
                                   const int*   __restrict__ n_ids) {
    int gid = blockIdx.x;
    int map = gid >> 9;
    int bc  = gid & 511;
    int b   = bc >> 6;
    int c   = bc & 63;

    const float* feat = (map ? fk : fq) + ((size_t)b * Cn + c) * HW;
    float* dst = g_diff + ((size_t)(map * Bn + b) * Cn + c) * Sn;

    int j = threadIdx.x;
    float fc = __ldg(&feat[c_ids[j]]);

#pragma unroll
    for (int off = 0; off < 8; off++) {
        int s = off * 256 + j;
        dst[s] = fc - __ldg(&feat[n_ids[s]]);
    }
}

// ---------------------------------------------------------------------------
// Kernel B: MLP + L2-normalize (f32x2).  grid = 256, 128 threads,
// each thread owns one row entirely.
// ---------------------------------------------------------------------------
#define XPAD 68
__global__ __launch_bounds__(128) void mlp_kernel(const float* __restrict__ W0,
                                                  const float* __restrict__ b0,
                                                  const float* __restrict__ W1,
                                                  const float* __restrict__ b1) {
    extern __shared__ float smem[];
    float* sx  = smem;                       // 128*68
    float* sW0 = sx + 128 * XPAD;            // 64*64  (transposed: [t][c])
    float* sW1 = sW0 + 64 * 64;              // 64*16
    float* sb0 = sW1 + 64 * 16;              // 64
    float* sb1 = sb0 + 64;                   // 16

    int mb = blockIdx.x >> 4;
    int s0 = (blockIdx.x & 15) * 128;
    int tid = threadIdx.x;

    const float* src = g_diff + (size_t)mb * Cn * Sn;

    for (int i = tid; i < 4096; i += 128) {
        int c = i >> 6, t = i & 63;
        sW0[t * 64 + c] = __ldg(&W0[i]);
    }
    for (int i = tid; i < 1024; i += 128) sW1[i] = __ldg(&W1[i]);
    if (tid < 64) sb0[tid] = __ldg(&b0[tid]);
    if (tid < 16) sb1[tid] = __ldg(&b1[tid]);

    for (int i = tid; i < 64 * 128; i += 128) {
        int c = i >> 7, s = i & 127;
        sx[s * XPAD + c] = src[(size_t)c * Sn + s0 + s];
    }
    __syncthreads();

    // pack this thread's 64 inputs into 32 f32x2 pairs
    ull x2[32];
#pragma unroll
    for (int i = 0; i < 16; i++) {
        float4 v = *reinterpret_cast<float4*>(&sx[tid * XPAD + i * 4]);
        x2[2 * i + 0] = pack2(v.x, v.y);
        x2[2 * i + 1] = pack2(v.z, v.w);
    }

    ull o2[8];
#pragma unroll
    for (int i = 0; i < 8; i++) o2[i] = pack2(sb1[2 * i], sb1[2 * i + 1]);

#pragma unroll 4
    for (int t = 0; t < 64; t++) {
        const ull* w2 = reinterpret_cast<const ull*>(&sW0[t * 64]);
        ull a0 = 0, a1 = 0, a2 = 0, a3 = 0;   // 0ull == packed (0,0)
#pragma unroll
        for (int i = 0; i < 8; i++) {
            FMA2(a0, x2[i +  0], w2[i +  0]);
            FMA2(a1, x2[i +  8], w2[i +  8]);
            FMA2(a2, x2[i + 16], w2[i + 16]);
            FMA2(a3, x2[i + 24], w2[i + 24]);
        }
        ADD2(a0, a1); ADD2(a2, a3); ADD2(a0, a2);
        float lo, hi; unpack2(a0, lo, hi);
        float h = fmaxf(lo + hi + sb0[t], 0.0f);
        ull h2 = pack2(h, h);
        const ull* w1 = reinterpret_cast<const ull*>(&sW1[t * 16]);
#pragma unroll
        for (int i = 0; i < 8; i++) FMA2(o2[i], h2, w1[i]);
    }

    float o[16];
#pragma unroll
    for (int i = 0; i < 8; i++) unpack2(o2[i], o[2 * i], o[2 * i + 1]);

    float sq = 0.f;
#pragma unroll
    for (int i = 0; i < 16; i++) sq = fmaf(o[i], o[i], sq);
    float inv = 1.0f / (sqrtf(sq) + 1e-7f);

    float* dst = (mb < Bn ? g_fq + (size_t)mb * Sn * OUTC
                          : g_fk + (size_t)(mb - Bn) * Sn * OUTC)
                 + (size_t)(s0 + tid) * OUTC;
#pragma unroll
    for (int oo = 0; oo < 4; oo++) {
        float4 v = make_float4(o[oo * 4 + 0] * inv, o[oo * 4 + 1] * inv,
                               o[oo * 4 + 2] * inv, o[oo * 4 + 3] * inv);
        *reinterpret_cast<float4*>(&dst[oo * 4]) = v;
    }
}

// ---------------------------------------------------------------------------
// Kernel C: PatchNCE loss.
//   loss_row(b,s) = ln2*(log2(sum_s) - dss') + 1/tau,
//   sum_s = sum_t exp2(q'.k_t - SCALE),  q' = q * SCALE (prescaled),
//   dss' = q'.k_s.   8 rows per warp, pairwise-packed f32x2.
//   k stored in smem swizzled: chunk j of row t at (j ^ ((t>>1)&3)).
//   grid = B*32, 256 threads (8 warps x 8 rows = 64 rows/block).
// ---------------------------------------------------------------------------
__global__ __launch_bounds__(256, 1) void loss_kernel(float* __restrict__ out) {
    extern __shared__ float shk[];   // 2048 rows x 16 floats, swizzled chunks
    int b    = blockIdx.x >> 5;
    int tile = blockIdx.x & 31;

    const float* fkb = g_fk + (size_t)b * Sn * OUTC;
    const float* fqb = g_fq + (size_t)b * Sn * OUTC;

    // stage fk[b] with chunk swizzle (conflict-free for both STS and LDS)
    const float4* fkb4 = reinterpret_cast<const float4*>(fkb);
    for (int i = threadIdx.x; i < Sn * 4; i += blockDim.x) {
        int t = i >> 2, j = i & 3;
        float4 v = fkb4[i];
        int jj = j ^ ((t >> 1) & 3);
        *reinterpret_cast<float4*>(&shk[t * 16 + jj * 4]) = v;
    }
    __syncthreads();

    int w    = threadIdx.x >> 5;
    int lane = threadIdx.x & 31;
    int s0   = tile * 64 + w * 8;

    // load 8 q rows, prescale by SCALE, pack row-pairs
    ull q2[4][16];
#pragma unroll
    for (int p = 0; p < 4; p++) {
        const float* qa = fqb + (size_t)(s0 + 2 * p + 0) * OUTC;
        const float* qb = fqb + (size_t)(s0 + 2 * p + 1) * OUTC;
#pragma unroll
        for (int c = 0; c < 16; c++)
            q2[p][c] = pack2(__ldg(&qa[c]) * F_SCALE, __ldg(&qb[c]) * F_SCALE);
    }

    const ull C2 = pack2(-F_SCALE, -F_SCALE);
    ull sum2[4] = {0ull, 0ull, 0ull, 0ull};

    for (int t = lane; t < Sn; t += 32) {
        const float* kb = &shk[t * 16];
        int sw = (t >> 1) & 3;
        float4 k0 = *reinterpret_cast<const float4*>(&kb[(0 ^ sw) * 4]);
        float4 k1 = *reinterpret_cast<const float4*>(&kb[(1 ^ sw) * 4]);
        float4 k2 = *reinterpret_cast<const float4*>(&kb[(2 ^ sw) * 4]);
        float4 k3 = *reinterpret_cast<const float4*>(&kb[(3 ^ sw) * 4]);
        ull kk2[16];
        kk2[ 0] = pack2(k0.x, k0.x); kk2[ 1] = pack2(k0.y, k0.y);
        kk2[ 2] = pack2(k0.z, k0.z); kk2[ 3] = pack2(k0.w, k0.w);
        kk2[ 4] = pack2(k1.x, k1.x); kk2[ 5] = pack2(k1.y, k1.y);
        kk2[ 6] = pack2(k1.z, k1.z); kk2[ 7] = pack2(k1.w, k1.w);
        kk2[ 8] = pack2(k2.x, k2.x); kk2[ 9] = pack2(k2.y, k2.y);
        kk2[10] = pack2(k2.z, k2.z); kk2[11] = pack2(k2.w, k2.w);
        kk2[12] = pack2(k3.x, k3.x); kk2[13] = pack2(k3.y, k3.y);
        kk2[14] = pack2(k3.z, k3.z); kk2[15] = pack2(k3.w, k3.w);

        ull d0 = C2, d1 = C2, d2 = C2, d3 = C2;
#pragma unroll
        for (int c = 0; c < 16; c++) {
            FMA2(d0, q2[0][c], kk2[c]);
            FMA2(d1, q2[1][c], kk2[c]);
            FMA2(d2, q2[2][c], kk2[c]);
            FMA2(d3, q2[3][c], kk2[c]);
        }
        float lo, hi;
        unpack2(d0, lo, hi); ull e0 = pack2(ex2f(lo), ex2f(hi)); ADD2(sum2[0], e0);
        unpack2(d1, lo, hi); ull e1 = pack2(ex2f(lo), ex2f(hi)); ADD2(sum2[1], e1);
        unpack2(d2, lo, hi); ull e2 = pack2(ex2f(lo), ex2f(hi)); ADD2(sum2[2], e2);
        unpack2(d3, lo, hi); ull e3 = pack2(ex2f(lo), ex2f(hi)); ADD2(sum2[3], e3);
    }

    // 8 row sums -> warp reduce
    float sum[8];
#pragma unroll
    for (int p = 0; p < 4; p++) unpack2(sum2[p], sum[2 * p], sum[2 * p + 1]);
#pragma unroll
    for (int r = 0; r < 8; r++) {
#pragma unroll
        for (int o = 16; o > 0; o >>= 1)
            sum[r] += __shfl_xor_sync(0xFFFFFFFFu, sum[r], o);
    }

    if (lane == 0) {
        float acc = 0.f;
#pragma unroll
        for (int r = 0; r < 8; r++) {
            int s = s0 + r;
            // dss' = q'[r] . k[s]  (swizzled smem read)
            int sw = (s >> 1) & 3;
            const float* ks = &shk[s * 16];
            float d = 0.f;
#pragma unroll
            for (int c = 0; c < 16; c++) {
                int j = c >> 2;
                float kv = ks[((j ^ sw) << 2) + (c & 3)];
                float qlo, qhi;
                unpack2(q2[r >> 1][c], qlo, qhi);
                d = fmaf((r & 1) ? qhi : qlo, kv, d);
            }
            acc += F_LN2 * (lg2f(sum[r]) - d) + F_INV_TAU;
        }
        atomicAdd(out, acc * (1.0f / (float)(Bn * Sn)));
    }
}

__global__ void zero_kernel(float* out) {
    if (threadIdx.x == 0) out[0] = 0.0f;
}

// ---------------------------------------------------------------------------
extern "C" void kernel_launch(void* const* d_in, const int* in_sizes, int n_in,
                              void* d_out, int out_size) {
    const float* f_q  = (const float*)d_in[0];
    const float* f_k  = (const float*)d_in[1];
    const float* W0   = (const float*)d_in[2];
    const float* b0   = (const float*)d_in[3];
    const float* W1   = (const float*)d_in[4];
    const float* b1   = (const float*)d_in[5];
    const int*   c_id = (const int*)d_in[6];
    const int*   n_id = (const int*)d_in[7];
    float* out = (float*)d_out;

    int mlp_smem = (128 * XPAD + 64 * 64 + 64 * 16 + 64 + 16) * (int)sizeof(float);
    cudaFuncSetAttribute(mlp_kernel,
                         cudaFuncAttributeMaxDynamicSharedMemorySize, mlp_smem);
    cudaFuncSetAttribute(loss_kernel,
                         cudaFuncAttributeMaxDynamicSharedMemorySize,
                         Sn * OUTC * (int)sizeof(float));

    gather_diff_kernel<<<2 * Bn * Cn, 256>>>(f_q, f_k, c_id, n_id);
    mlp_kernel<<<16 * 16, 128, mlp_smem>>>(W0, b0, W1, b1);
    zero_kernel<<<1, 32>>>(out);
    loss_kernel<<<Bn * 32, 256, Sn * OUTC * (int)sizeof(float)>>>(out);
}

// round 4
// speedup vs baseline: 1.9786x; 1.0205x over previous
#include <cuda_runtime.h>
#include <math.h>

#define Bn 8
#define Cn 64
#define HW 65536
#define Sn 2048
#define OUTC 16

#define F_INV_TAU   14.2857142857142857f          /* 1/0.07 */
#define F_SCALE     20.6096954f                   /* log2(e)/0.07 */
#define F_LN2       0.69314718056f

// f32x2 packed helpers ------------------------------------------------------
typedef unsigned long long ull;
__device__ __forceinline__ ull pack2(float lo, float hi) {
    ull r;
    asm("mov.b64 %0, {%1, %2};" : "=l"(r) : "r"(__float_as_uint(lo)), "r"(__float_as_uint(hi)));
    return r;
}
__device__ __forceinline__ void unpack2(ull v, float& lo, float& hi) {
    unsigned a, b;
    asm("mov.b64 {%0, %1}, %2;" : "=r"(a), "=r"(b) : "l"(v));
    lo = __uint_as_float(a); hi = __uint_as_float(b);
}
#define FMA2(d, a, b) asm("fma.rn.f32x2 %0, %1, %2, %3;" : "=l"(d) : "l"(a), "l"(b), "l"(d))
#define ADD2(d, a)    asm("add.rn.f32x2 %0, %1, %2;"     : "=l"(d) : "l"(a), "l"(d))
__device__ __forceinline__ float ex2f(float x) {
    float y; asm("ex2.approx.f32 %0, %1;" : "=f"(y) : "f"(x)); return y;
}
__device__ __forceinline__ float lg2f(float x) {
    float y; asm("lg2.approx.f32 %0, %1;" : "=f"(y) : "f"(x)); return y;
}

// Scratch
__device__ float g_diff[2 * Bn * Cn * Sn];      // 8 MB
__device__ float g_fq[Bn * Sn * OUTC];
__device__ float g_fk[Bn * Sn * OUTC];

// ---------------------------------------------------------------------------
// Kernel A: gather + diff.  grid = 2*B*C = 1024 blocks, 256 threads.
// ---------------------------------------------------------------------------
__global__ void gather_diff_kernel(const float* __restrict__ fq,
                                   const float* __restrict__ fk,
                                   const int*   __restrict__ c_ids,
                                   const int*   __restrict__ n_ids) {
    int gid = blockIdx.x;
    int map = gid >> 9;
    int bc  = gid & 511;
    int b   = bc >> 6;
    int c   = bc & 63;

    const float* feat = (map ? fk : fq) + ((size_t)b * Cn + c) * HW;
    float* dst = g_diff + ((size_t)(map * Bn + b) * Cn + c) * Sn;

    int j = threadIdx.x;
    float fc = __ldg(&feat[c_ids[j]]);

#pragma unroll
    for (int off = 0; off < 8; off++) {
        int s = off * 256 + j;
        dst[s] = fc - __ldg(&feat[n_ids[s]]);
    }
}

// ---------------------------------------------------------------------------
// Kernel B: MLP + L2-normalize (f32x2).  grid = 256, 128 threads,
// each thread owns one row entirely.
// ---------------------------------------------------------------------------
#define XPAD 68
__global__ __launch_bounds__(128) void mlp_kernel(const float* __restrict__ W0,
                                                  const float* __restrict__ b0,
                                                  const float* __restrict__ W1,
                                                  const float* __restrict__ b1) {
    extern __shared__ float smem[];
    float* sx  = smem;                       // 128*68
    float* sW0 = sx + 128 * XPAD;            // 64*64  (transposed: [t][c])
    float* sW1 = sW0 + 64 * 64;              // 64*16
    float* sb0 = sW1 + 64 * 16;              // 64
    float* sb1 = sb0 + 64;                   // 16

    int mb = blockIdx.x >> 4;
    int s0 = (blockIdx.x & 15) * 128;
    int tid = threadIdx.x;

    const float* src = g_diff + (size_t)mb * Cn * Sn;

    for (int i = tid; i < 4096; i += 128) {
        int c = i >> 6, t = i & 63;
        sW0[t * 64 + c] = __ldg(&W0[i]);
    }
    for (int i = tid; i < 1024; i += 128) sW1[i] = __ldg(&W1[i]);
    if (tid < 64) sb0[tid] = __ldg(&b0[tid]);
    if (tid < 16) sb1[tid] = __ldg(&b1[tid]);

    for (int i = tid; i < 64 * 128; i += 128) {
        int c = i >> 7, s = i & 127;
        sx[s * XPAD + c] = src[(size_t)c * Sn + s0 + s];
    }
    __syncthreads();

    ull x2[32];
#pragma unroll
    for (int i = 0; i < 16; i++) {
        float4 v = *reinterpret_cast<float4*>(&sx[tid * XPAD + i * 4]);
        x2[2 * i + 0] = pack2(v.x, v.y);
        x2[2 * i + 1] = pack2(v.z, v.w);
    }

    ull o2[8];
#pragma unroll
    for (int i = 0; i < 8; i++) o2[i] = pack2(sb1[2 * i], sb1[2 * i + 1]);

#pragma unroll 4
    for (int t = 0; t < 64; t++) {
        const ull* w2 = reinterpret_cast<const ull*>(&sW0[t * 64]);
        ull a0 = 0, a1 = 0, a2 = 0, a3 = 0;
#pragma unroll
        for (int i = 0; i < 8; i++) {
            FMA2(a0, x2[i +  0], w2[i +  0]);
            FMA2(a1, x2[i +  8], w2[i +  8]);
            FMA2(a2, x2[i + 16], w2[i + 16]);
            FMA2(a3, x2[i + 24], w2[i + 24]);
        }
        ADD2(a0, a1); ADD2(a2, a3); ADD2(a0, a2);
        float lo, hi; unpack2(a0, lo, hi);
        float h = fmaxf(lo + hi + sb0[t], 0.0f);
        ull h2 = pack2(h, h);
        const ull* w1 = reinterpret_cast<const ull*>(&sW1[t * 16]);
#pragma unroll
        for (int i = 0; i < 8; i++) FMA2(o2[i], h2, w1[i]);
    }

    float o[16];
#pragma unroll
    for (int i = 0; i < 8; i++) unpack2(o2[i], o[2 * i], o[2 * i + 1]);

    float sq = 0.f;
#pragma unroll
    for (int i = 0; i < 16; i++) sq = fmaf(o[i], o[i], sq);
    float inv = 1.0f / (sqrtf(sq) + 1e-7f);

    float* dst = (mb < Bn ? g_fq + (size_t)mb * Sn * OUTC
                          : g_fk + (size_t)(mb - Bn) * Sn * OUTC)
                 + (size_t)(s0 + tid) * OUTC;
#pragma unroll
    for (int oo = 0; oo < 4; oo++) {
        float4 v = make_float4(o[oo * 4 + 0] * inv, o[oo * 4 + 1] * inv,
                               o[oo * 4 + 2] * inv, o[oo * 4 + 3] * inv);
        *reinterpret_cast<float4*>(&dst[oo * 4]) = v;
    }
}

// ---------------------------------------------------------------------------
// Kernel C: PatchNCE loss (v3 — occupancy fix).
//   loss_row(b,s) = ln2*(log2(sum_s) - dss') + 1/tau,
//   sum_s = sum_t exp2(q'.k_t - SCALE),  q' prescaled by SCALE = log2e/tau.
//   512 threads = 16 warps x 4 rows = 64 rows/block; grid = B*32.
//   q packed pairwise (2 pairs = 64 regs) -> ~105 regs -> 16 warps/SM.
//   k in 128KB smem, chunk-swizzled; per-4-channel pack-and-use keeps
//   k transients small.
// ---------------------------------------------------------------------------
__global__ __launch_bounds__(512, 1) void loss_kernel(float* __restrict__ out) {
    extern __shared__ float shk[];   // 2048 rows x 16 floats, swizzled chunks
    int b    = blockIdx.x >> 5;
    int tile = blockIdx.x & 31;

    const float* fkb = g_fk + (size_t)b * Sn * OUTC;
    const float* fqb = g_fq + (size_t)b * Sn * OUTC;

    // stage fk[b] with chunk swizzle
    const float4* fkb4 = reinterpret_cast<const float4*>(fkb);
    for (int i = threadIdx.x; i < Sn * 4; i += blockDim.x) {
        int t = i >> 2, j = i & 3;
        float4 v = fkb4[i];
        int jj = j ^ ((t >> 1) & 3);
        *reinterpret_cast<float4*>(&shk[t * 16 + jj * 4]) = v;
    }
    __syncthreads();

    int w    = threadIdx.x >> 5;      // 0..15
    int lane = threadIdx.x & 31;
    int s0   = tile * 64 + w * 4;

    // 4 q rows, prescaled, packed into 2 row-pairs
    ull q2[2][16];
#pragma unroll
    for (int p = 0; p < 2; p++) {
        const float* qa = fqb + (size_t)(s0 + 2 * p + 0) * OUTC;
        const float* qb = fqb + (size_t)(s0 + 2 * p + 1) * OUTC;
#pragma unroll
        for (int c = 0; c < 16; c++)
            q2[p][c] = pack2(__ldg(&qa[c]) * F_SCALE, __ldg(&qb[c]) * F_SCALE);
    }

    const ull C2 = pack2(-F_SCALE, -F_SCALE);
    ull sum2[2] = {0ull, 0ull};

    for (int t = lane; t < Sn; t += 32) {
        const float* kb = &shk[t * 16];
        int sw = (t >> 1) & 3;
        ull d0 = C2, d1 = C2;
#pragma unroll
        for (int j = 0; j < 4; j++) {
            float4 k = *reinterpret_cast<const float4*>(&kb[((j ^ sw) << 2)]);
            ull ka = pack2(k.x, k.x);
            ull kb2 = pack2(k.y, k.y);
            ull kc = pack2(k.z, k.z);
            ull kd = pack2(k.w, k.w);
            FMA2(d0, q2[0][4 * j + 0], ka);  FMA2(d1, q2[1][4 * j + 0], ka);
            FMA2(d0, q2[0][4 * j + 1], kb2); FMA2(d1, q2[1][4 * j + 1], kb2);
            FMA2(d0, q2[0][4 * j + 2], kc);  FMA2(d1, q2[1][4 * j + 2], kc);
            FMA2(d0, q2[0][4 * j + 3], kd);  FMA2(d1, q2[1][4 * j + 3], kd);
        }
        float lo, hi;
        unpack2(d0, lo, hi); ull e0 = pack2(ex2f(lo), ex2f(hi)); ADD2(sum2[0], e0);
        unpack2(d1, lo, hi); ull e1 = pack2(ex2f(lo), ex2f(hi)); ADD2(sum2[1], e1);
    }

    // 4 row sums -> warp reduce
    float sum[4];
#pragma unroll
    for (int p = 0; p < 2; p++) unpack2(sum2[p], sum[2 * p], sum[2 * p + 1]);
#pragma unroll
    for (int r = 0; r < 4; r++) {
#pragma unroll
        for (int o = 16; o > 0; o >>= 1)
            sum[r] += __shfl_xor_sync(0xFFFFFFFFu, sum[r], o);
    }

    if (lane == 0) {
        float acc = 0.f;
#pragma unroll
        for (int r = 0; r < 4; r++) {
            int s = s0 + r;
            int sw = (s >> 1) & 3;
            const float* ks = &shk[s * 16];
            float d = 0.f;
#pragma unroll
            for (int c = 0; c < 16; c++) {
                int j = c >> 2;
                float kv = ks[((j ^ sw) << 2) + (c & 3)];
                float qlo, qhi;
                unpack2(q2[r >> 1][c], qlo, qhi);
                d = fmaf((r & 1) ? qhi : qlo, kv, d);
            }
            acc += F_LN2 * (lg2f(sum[r]) - d) + F_INV_TAU;
        }
        atomicAdd(out, acc * (1.0f / (float)(Bn * Sn)));
    }
}

__global__ void zero_kernel(float* out) {
    if (threadIdx.x == 0) out[0] = 0.0f;
}

// ---------------------------------------------------------------------------
extern "C" void kernel_launch(void* const* d_in, const int* in_sizes, int n_in,
                              void* d_out, int out_size) {
    const float* f_q  = (const float*)d_in[0];
    const float* f_k  = (const float*)d_in[1];
    const float* W0   = (const float*)d_in[2];
    const float* b0   = (const float*)d_in[3];
    const float* W1   = (const float*)d_in[4];
    const float* b1   = (const float*)d_in[5];
    const int*   c_id = (const int*)d_in[6];
    const int*   n_id = (const int*)d_in[7];
    float* out = (float*)d_out;

    int mlp_smem = (128 * XPAD + 64 * 64 + 64 * 16 + 64 + 16) * (int)sizeof(float);
    cudaFuncSetAttribute(mlp_kernel,
                         cudaFuncAttributeMaxDynamicSharedMemorySize, mlp_smem);
    cudaFuncSetAttribute(loss_kernel,
                         cudaFuncAttributeMaxDynamicSharedMemorySize,
                         Sn * OUTC * (int)sizeof(float));

    gather_diff_kernel<<<2 * Bn * Cn, 256>>>(f_q, f_k, c_id, n_id);
    mlp_kernel<<<16 * 16, 128, mlp_smem>>>(W0, b0, W1, b1);
    zero_kernel<<<1, 32>>>(out);
    loss_kernel<<<Bn * 32, 512, Sn * OUTC * (int)sizeof(float)>>>(out);
}